// round 15
// baseline (speedup 1.0000x reference)
#include <cuda_runtime.h>
#include <cuda_bf16.h>
#include <math.h>
#include <stdint.h>

#define N_NODES 100000
#define N_EDGES 800000
#define F_IN 256
#define HID 128
#define N_CLS 32
#define SCAN_BLOCKS 98   // ceil(100000/1024)

// fused agg1+gemm2 smem: As[128][132] + Bs[128][40], fp32
#define FUSED_AS_STRIDE 132
#define FUSED_SMEM_FLOATS (128 * FUSED_AS_STRIDE + 128 * 40)
#define FUSED_SMEM_BYTES (FUSED_SMEM_FLOATS * 4)

// ---------------- scratch (device globals; no allocation allowed) ----------------
__device__ int      g_flag;                 // 1 if edge_index is int64, 0 if int32
__device__ int      g_deg[N_NODES];         // in-degree of real edges
__device__ int      g_cursor[N_NODES];
__device__ int      g_rowstart[N_NODES];
__device__ int      g_blocksum[SCAN_BLOCKS];
__device__ int      g_blockoff[SCAN_BLOCKS];
__device__ int      g_csr_src[N_EDGES];     // src node per CSR slot (bucketed by dst)
__device__ float    g_dinv[N_NODES];
__device__ uint32_t g_xw_bf[N_NODES * 64];  // X @ W1, bf16x2 packed (128 bf16/row)
__device__ uint32_t g_hw2_bf[N_NODES * 16]; // (agg relu H) @ W2, bf16x2 (32 bf16/row)

__device__ __forceinline__ float2 bf2_to_f2(uint32_t u) {
    __nv_bfloat162 p = *reinterpret_cast<__nv_bfloat162*>(&u);
    return __bfloat1622float2(p);
}
__device__ __forceinline__ uint32_t f2_to_bf2(float x, float y) {
    __nv_bfloat162 p = __float22bfloat162_rn(make_float2(x, y));
    return *reinterpret_cast<uint32_t*>(&p);
}

// ---------------- init + edge dtype detection (fused) ----------------
__global__ __launch_bounds__(256)
void k_init(const int* e_as_i32) {
    int i = blockIdx.x * blockDim.x + threadIdx.x;
    if (i < N_NODES) { g_deg[i] = 0; g_cursor[i] = 0; }
    if (i == 0) {
        // int64 little-endian nonneg small values -> odd 32-bit words are all 0
        bool is64 = true;
        for (int j = 0; j < 64; j++) {
            if (e_as_i32[2 * j + 1] != 0) { is64 = false; break; }
        }
        g_flag = is64 ? 1 : 0;
    }
}

// degree count only (reads dst half of edge_index directly)
__global__ __launch_bounds__(256)
void k_convert(const void* eidx) {
    int e = blockIdx.x * blockDim.x + threadIdx.x;
    if (e >= N_EDGES) return;
    int d;
    if (g_flag) {
        d = (int)((const long long*)eidx)[N_EDGES + e];
    } else {
        d = ((const int*)eidx)[N_EDGES + e];
    }
    atomicAdd(&g_deg[d], 1);
}

// ---------------- device-wide exclusive scan of g_deg, 3 phases ----------------
__device__ __forceinline__ int warp_incl_scan(int x, int lane) {
#pragma unroll
    for (int off = 1; off < 32; off <<= 1) {
        int y = __shfl_up_sync(0xFFFFFFFFu, x, off);
        if (lane >= off) x += y;
    }
    return x;
}

__global__ __launch_bounds__(1024)
void k_scan_a() {
    const int t = threadIdx.x;
    const int lane = t & 31, wid = t >> 5;
    const int i = blockIdx.x * 1024 + t;
    int v = (i < N_NODES) ? g_deg[i] : 0;
    int x = warp_incl_scan(v, lane);
    __shared__ int wsum[32];
    if (lane == 31) wsum[wid] = x;
    __syncthreads();
    if (wid == 0) {
        int s = wsum[lane];
        s = warp_incl_scan(s, lane);
        wsum[lane] = s;
    }
    __syncthreads();
    int ex = x - v + (wid > 0 ? wsum[wid - 1] : 0);
    if (i < N_NODES) g_rowstart[i] = ex;
    if (t == 1023) g_blocksum[blockIdx.x] = ex + v;
}

__global__ __launch_bounds__(128)
void k_scan_b() {
    const int t = threadIdx.x;
    const int lane = t & 31, wid = t >> 5;
    int v = (t < SCAN_BLOCKS) ? g_blocksum[t] : 0;
    int x = warp_incl_scan(v, lane);
    __shared__ int wsum[4];
    if (lane == 31) wsum[wid] = x;
    __syncthreads();
    int add = 0;
#pragma unroll
    for (int w = 0; w < 4; w++)
        if (w < wid) add += wsum[w];
    if (t < SCAN_BLOCKS) g_blockoff[t] = x - v + add;
}

__global__ __launch_bounds__(1024)
void k_scan_c() {
    const int i = blockIdx.x * 1024 + threadIdx.x;
    if (i < N_NODES) {
        g_rowstart[i] += g_blockoff[blockIdx.x];
        g_dinv[i] = rsqrtf((float)(g_deg[i] + 1));  // +1 self loop
    }
}

// CSR bucket fill, reading src/dst directly from edge_index
__global__ __launch_bounds__(256)
void k_fill(const void* eidx) {
    int e = blockIdx.x * blockDim.x + threadIdx.x;
    if (e >= N_EDGES) return;
    int s, d;
    if (g_flag) {
        const long long* p = (const long long*)eidx;
        s = (int)p[e];
        d = (int)p[N_EDGES + e];
    } else {
        const int* p = (const int*)eidx;
        s = p[e];
        d = p[N_EDGES + e];
    }
    int pos = atomicAdd(&g_cursor[d], 1);
    g_csr_src[g_rowstart[d] + pos] = s;
}

// ---------------- tf32 helpers ----------------
__device__ __forceinline__ float to_tf32(float x) {
    float r;
    asm("cvt.rna.tf32.f32 %0, %1;" : "=f"(r) : "f"(x));
    return r;
}

__device__ __forceinline__ void mma_tf32(float c[4], const uint32_t a[4], const uint32_t b[2]) {
    asm volatile(
        "mma.sync.aligned.m16n8k8.row.col.f32.tf32.tf32.f32 "
        "{%0,%1,%2,%3}, {%4,%5,%6,%7}, {%8,%9}, {%0,%1,%2,%3};"
        : "+f"(c[0]), "+f"(c[1]), "+f"(c[2]), "+f"(c[3])
        : "r"(a[0]), "r"(a[1]), "r"(a[2]), "r"(a[3]), "r"(b[0]), "r"(b[1]));
}

// ---------------- GEMM1: XW1 via tf32 MMA, bf16 output ----------------
__global__ __launch_bounds__(256)
void k_gemm1_tf32(const float* __restrict__ A, const float* __restrict__ B) {
    __shared__ float As[128][36];
    __shared__ float Bs[32][136];

    const int tid = threadIdx.x;
    const int m0 = blockIdx.x * 128;
    const int wid = tid >> 5, lane = tid & 31;
    const int g = lane >> 2, tig = lane & 3;
    const int warp_m = wid >> 1;
    const int warp_n = wid & 1;
    const int mbase = warp_m * 32;
    const int nbase = warp_n * 64;

    float c[2][8][4];
#pragma unroll
    for (int mt = 0; mt < 2; mt++)
#pragma unroll
        for (int nt = 0; nt < 8; nt++)
#pragma unroll
            for (int i = 0; i < 4; i++) c[mt][nt][i] = 0.0f;

    for (int k0 = 0; k0 < F_IN; k0 += 32) {
#pragma unroll
        for (int s = 0; s < 4; s++) {
            int slot = tid + s * 256;
            int r = slot >> 3;
            int kk = (slot & 7) * 4;
            int gr = m0 + r;
            float4 v = make_float4(0.f, 0.f, 0.f, 0.f);
            if (gr < N_NODES) v = *reinterpret_cast<const float4*>(&A[(size_t)gr * F_IN + k0 + kk]);
            As[r][kk + 0] = to_tf32(v.x);
            As[r][kk + 1] = to_tf32(v.y);
            As[r][kk + 2] = to_tf32(v.z);
            As[r][kk + 3] = to_tf32(v.w);
        }
#pragma unroll
        for (int s = 0; s < 4; s++) {
            int slot = tid + s * 256;
            int kr = slot >> 5;
            int n = (slot & 31) * 4;
            float4 v = *reinterpret_cast<const float4*>(&B[(size_t)(k0 + kr) * HID + n]);
            Bs[kr][n + 0] = to_tf32(v.x);
            Bs[kr][n + 1] = to_tf32(v.y);
            Bs[kr][n + 2] = to_tf32(v.z);
            Bs[kr][n + 3] = to_tf32(v.w);
        }
        __syncthreads();

#pragma unroll
        for (int kk = 0; kk < 4; kk++) {
            const int kb = kk * 8;
            uint32_t a[2][4];
#pragma unroll
            for (int mt = 0; mt < 2; mt++) {
                int m = mbase + mt * 16 + g;
                a[mt][0] = __float_as_uint(As[m][kb + tig]);
                a[mt][1] = __float_as_uint(As[m + 8][kb + tig]);
                a[mt][2] = __float_as_uint(As[m][kb + tig + 4]);
                a[mt][3] = __float_as_uint(As[m + 8][kb + tig + 4]);
            }
            uint32_t b[8][2];
#pragma unroll
            for (int nt = 0; nt < 8; nt++) {
                int n = nbase + nt * 8 + g;
                b[nt][0] = __float_as_uint(Bs[kb + tig][n]);
                b[nt][1] = __float_as_uint(Bs[kb + tig + 4][n]);
            }
#pragma unroll
            for (int mt = 0; mt < 2; mt++)
#pragma unroll
                for (int nt = 0; nt < 8; nt++)
                    mma_tf32(c[mt][nt], a[mt], b[nt]);
        }
        __syncthreads();
    }

#pragma unroll
    for (int mt = 0; mt < 2; mt++) {
#pragma unroll
        for (int nt = 0; nt < 8; nt++) {
            int row0 = m0 + mbase + mt * 16 + g;
            int cp = (nbase + nt * 8) / 2 + tig;
            if (row0 < N_NODES)
                g_xw_bf[(size_t)row0 * 64 + cp] = f2_to_bf2(c[mt][nt][0], c[mt][nt][1]);
            int row1 = row0 + 8;
            if (row1 < N_NODES)
                g_xw_bf[(size_t)row1 * 64 + cp] = f2_to_bf2(c[mt][nt][2], c[mt][nt][3]);
        }
    }
}

// ---------------- FUSED: layer-1 aggregation + bias + relu + GEMM2 ----------------
// Block owns 128 nodes. Phase 1: 8 warps aggregate 16 nodes each into smem As
// (tf32). Phase 2: tf32 MMA with W2 (cached in Bs), bf16 output to g_hw2_bf.
__global__ __launch_bounds__(256)
void k_agg1_gemm2(const float* __restrict__ b1, const float* __restrict__ W2) {
    extern __shared__ float smem[];
    float (*As)[FUSED_AS_STRIDE] = reinterpret_cast<float(*)[FUSED_AS_STRIDE]>(smem);
    float (*Bs)[40] = reinterpret_cast<float(*)[40]>(smem + 128 * FUSED_AS_STRIDE);

    const int tid = threadIdx.x;
    const int m0 = blockIdx.x * 128;
    const int wid = tid >> 5, lane = tid & 31;
    const int g = lane >> 2, tig = lane & 3;

    // load whole W2 (128x32) into Bs, tf32
#pragma unroll
    for (int s = 0; s < 4; s++) {
        int slot = tid + s * 256;
        int r = slot >> 3;
        int n = (slot & 7) * 4;
        float4 v = *reinterpret_cast<const float4*>(&W2[(size_t)r * N_CLS + n]);
        Bs[r][n + 0] = to_tf32(v.x);
        Bs[r][n + 1] = to_tf32(v.y);
        Bs[r][n + 2] = to_tf32(v.z);
        Bs[r][n + 3] = to_tf32(v.w);
    }

    // phase 1: aggregation (warp per node, 16 nodes per warp)
    const uint2* xw2 = reinterpret_cast<const uint2*>(g_xw_bf);  // 32 uint2 per node
    float4 bb = reinterpret_cast<const float4*>(b1)[lane];
    for (int i = 0; i < 16; i++) {
        int local = wid * 16 + i;
        int node = m0 + local;
        float4 acc = make_float4(0.f, 0.f, 0.f, 0.f);
        if (node < N_NODES) {
            float di = g_dinv[node];
            uint2 sv = xw2[(size_t)node * 32 + lane];
            float2 s0 = bf2_to_f2(sv.x), s1 = bf2_to_f2(sv.y);
            float w0 = di * di;
            acc = make_float4(s0.x * w0, s0.y * w0, s1.x * w0, s1.y * w0);
            int start = g_rowstart[node];
            int cnt = g_deg[node];
#pragma unroll 4
            for (int e = 0; e < cnt; e++) {
                int s = g_csr_src[start + e];
                float w = di * g_dinv[s];
                uint2 v = xw2[(size_t)s * 32 + lane];
                float2 f0 = bf2_to_f2(v.x), f1 = bf2_to_f2(v.y);
                acc.x += w * f0.x;
                acc.y += w * f0.y;
                acc.z += w * f1.x;
                acc.w += w * f1.y;
            }
            acc.x = to_tf32(fmaxf(acc.x + bb.x, 0.0f));
            acc.y = to_tf32(fmaxf(acc.y + bb.y, 0.0f));
            acc.z = to_tf32(fmaxf(acc.z + bb.z, 0.0f));
            acc.w = to_tf32(fmaxf(acc.w + bb.w, 0.0f));
        }
        // As[local][lane*4 .. lane*4+3]; 16B aligned, conflict-free STS.128
        *reinterpret_cast<float4*>(&As[local][lane * 4]) = acc;
    }
    __syncthreads();

    // phase 2: MMA. Each warp: rows wid*16..wid*16+15, full N=32.
    float c[4][4];
#pragma unroll
    for (int nt = 0; nt < 4; nt++)
#pragma unroll
        for (int i = 0; i < 4; i++) c[nt][i] = 0.0f;

    const int m = wid * 16 + g;
#pragma unroll
    for (int k0 = 0; k0 < HID; k0 += 32) {
#pragma unroll
        for (int kk = 0; kk < 4; kk++) {
            const int kb = k0 + kk * 8;
            uint32_t a[4];
            a[0] = __float_as_uint(As[m][kb + tig]);
            a[1] = __float_as_uint(As[m + 8][kb + tig]);
            a[2] = __float_as_uint(As[m][kb + tig + 4]);
            a[3] = __float_as_uint(As[m + 8][kb + tig + 4]);
#pragma unroll
            for (int nt = 0; nt < 4; nt++) {
                uint32_t b[2];
                int n = nt * 8 + g;
                b[0] = __float_as_uint(Bs[kb + tig][n]);
                b[1] = __float_as_uint(Bs[kb + tig + 4][n]);
                mma_tf32(c[nt], a, b);
            }
        }
    }

    const int row0 = m0 + wid * 16 + g;
#pragma unroll
    for (int nt = 0; nt < 4; nt++) {
        int cp = nt * 4 + tig;
        if (row0 < N_NODES)
            g_hw2_bf[(size_t)row0 * 16 + cp] = f2_to_bf2(c[nt][0], c[nt][1]);
        if (row0 + 8 < N_NODES)
            g_hw2_bf[(size_t)(row0 + 8) * 16 + cp] = f2_to_bf2(c[nt][2], c[nt][3]);
    }
}

// ---------------- layer-2 aggregation + bias + log_softmax ----------------
__global__ __launch_bounds__(256)
void k_agg2(const float* __restrict__ b2, float* __restrict__ out) {
    int node = (blockIdx.x * blockDim.x + threadIdx.x) >> 5;
    int lane = threadIdx.x & 31;
    if (node >= N_NODES) return;
    float di = g_dinv[node];
    const __nv_bfloat16* hw = reinterpret_cast<const __nv_bfloat16*>(g_hw2_bf);
    float acc = di * di * __bfloat162float(hw[(size_t)node * N_CLS + lane]);
    int start = g_rowstart[node];
    int cnt = g_deg[node];
#pragma unroll 4
    for (int e = 0; e < cnt; e++) {
        int s = g_csr_src[start + e];
        float w = di * g_dinv[s];
        acc += w * __bfloat162float(hw[(size_t)s * N_CLS + lane]);
    }
    acc += b2[lane];
    // log_softmax over the 32 lanes
    float m = acc;
#pragma unroll
    for (int off = 16; off > 0; off >>= 1)
        m = fmaxf(m, __shfl_xor_sync(0xFFFFFFFFu, m, off));
    float ex = expf(acc - m);
    float sum = ex;
#pragma unroll
    for (int off = 16; off > 0; off >>= 1)
        sum += __shfl_xor_sync(0xFFFFFFFFu, sum, off);
    out[(size_t)node * N_CLS + lane] = acc - m - logf(sum);
}

// ---------------- launch ----------------
extern "C" void kernel_launch(void* const* d_in, const int* in_sizes, int n_in,
                              void* d_out, int out_size) {
    const float* features = nullptr;
    const void*  eidx = nullptr;
    const float* W1 = nullptr;
    const float* b1 = nullptr;
    const float* W2 = nullptr;
    const float* b2 = nullptr;
    for (int i = 0; i < n_in; i++) {
        switch (in_sizes[i]) {
            case N_NODES * F_IN: features = (const float*)d_in[i]; break;
            case 2 * N_EDGES:    eidx = d_in[i]; break;
            case F_IN * HID:     W1 = (const float*)d_in[i]; break;
            case HID:            b1 = (const float*)d_in[i]; break;
            case HID * N_CLS:    W2 = (const float*)d_in[i]; break;
            case N_CLS:          b2 = (const float*)d_in[i]; break;
            default: break;
        }
    }

    // one-time host-side setup (not a stream op; safe under capture)
    static cudaStream_t s2 = nullptr;
    static cudaEvent_t ev_fork = nullptr, ev_join = nullptr;
    if (s2 == nullptr) {
        cudaStreamCreateWithFlags(&s2, cudaStreamNonBlocking);
        cudaEventCreateWithFlags(&ev_fork, cudaEventDisableTiming);
        cudaEventCreateWithFlags(&ev_join, cudaEventDisableTiming);
        cudaFuncSetAttribute(k_agg1_gemm2,
                             cudaFuncAttributeMaxDynamicSharedMemorySize,
                             FUSED_SMEM_BYTES);
    }

    // fork: preprocessing chain on s2 (launched first), GEMM1 on the main stream
    cudaEventRecord(ev_fork, 0);
    cudaStreamWaitEvent(s2, ev_fork, 0);

    k_init<<<(N_NODES + 255) / 256, 256, 0, s2>>>((const int*)eidx);
    k_convert<<<(N_EDGES + 255) / 256, 256, 0, s2>>>(eidx);
    k_scan_a<<<SCAN_BLOCKS, 1024, 0, s2>>>();
    k_scan_b<<<1, 128, 0, s2>>>();
    k_scan_c<<<SCAN_BLOCKS, 1024, 0, s2>>>();
    k_fill<<<(N_EDGES + 255) / 256, 256, 0, s2>>>(eidx);
    cudaEventRecord(ev_join, s2);

    // concurrent with preprocessing: layer-1 GEMM (tf32 tensor cores)
    {
        int grid = (N_NODES + 127) / 128;  // 782
        k_gemm1_tf32<<<grid, 256>>>(features, W1);
    }

    // join: fused agg1+gemm2 needs both GEMM1 output and CSR
    cudaStreamWaitEvent(0, ev_join, 0);

    {
        int grid = (N_NODES + 127) / 128;  // 782
        k_agg1_gemm2<<<grid, 256, FUSED_SMEM_BYTES>>>(b1, W2);
    }
    k_agg2<<<(N_NODES * 32 + 255) / 256, 256>>>(b2, (float*)d_out);
}

// round 17
// speedup vs baseline: 1.5156x; 1.5156x over previous
#include <cuda_runtime.h>
#include <cuda_bf16.h>
#include <math.h>
#include <stdint.h>

#define N_NODES 100000
#define N_EDGES 800000
#define F_IN 256
#define HID 128
#define N_CLS 32
#define SCAN_BLOCKS 98   // ceil(100000/1024)

// ---------------- scratch (device globals; no allocation allowed) ----------------
__device__ int      g_flag;                 // 1 if edge_index is int64, 0 if int32
__device__ int      g_deg[N_NODES];         // in-degree of real edges
__device__ int      g_cursor[N_NODES];
__device__ int      g_rowstart[N_NODES];
__device__ int      g_blocksum[SCAN_BLOCKS];
__device__ int      g_blockoff[SCAN_BLOCKS];
__device__ int      g_csr_src[N_EDGES];     // src node per CSR slot (bucketed by dst)
__device__ float    g_dinv[N_NODES];
__device__ uint32_t g_xw_bf[N_NODES * 64];  // X @ W1, bf16x2 packed (128 bf16/row)
__device__ uint32_t g_h_bf[N_NODES * 64];   // layer-1 output (post relu), bf16x2
__device__ uint32_t g_hw2_bf[N_NODES * 16]; // H @ W2, bf16x2 packed (32 bf16/row)

__device__ __forceinline__ float2 bf2_to_f2(uint32_t u) {
    __nv_bfloat162 p = *reinterpret_cast<__nv_bfloat162*>(&u);
    return __bfloat1622float2(p);
}
__device__ __forceinline__ uint32_t f2_to_bf2(float x, float y) {
    __nv_bfloat162 p = __float22bfloat162_rn(make_float2(x, y));
    return *reinterpret_cast<uint32_t*>(&p);
}

// ---------------- init + edge dtype detection (fused) ----------------
__global__ __launch_bounds__(256)
void k_init(const int* e_as_i32) {
    int i = blockIdx.x * blockDim.x + threadIdx.x;
    if (i < N_NODES) { g_deg[i] = 0; g_cursor[i] = 0; }
    if (i == 0) {
        // int64 little-endian nonneg small values -> odd 32-bit words are all 0
        bool is64 = true;
        for (int j = 0; j < 64; j++) {
            if (e_as_i32[2 * j + 1] != 0) { is64 = false; break; }
        }
        g_flag = is64 ? 1 : 0;
    }
}

// degree count only (reads dst half of edge_index directly)
__global__ __launch_bounds__(256)
void k_convert(const void* eidx) {
    int e = blockIdx.x * blockDim.x + threadIdx.x;
    if (e >= N_EDGES) return;
    int d;
    if (g_flag) {
        d = (int)((const long long*)eidx)[N_EDGES + e];
    } else {
        d = ((const int*)eidx)[N_EDGES + e];
    }
    atomicAdd(&g_deg[d], 1);
}

// ---------------- device-wide exclusive scan of g_deg, 3 phases ----------------
__device__ __forceinline__ int warp_incl_scan(int x, int lane) {
#pragma unroll
    for (int off = 1; off < 32; off <<= 1) {
        int y = __shfl_up_sync(0xFFFFFFFFu, x, off);
        if (lane >= off) x += y;
    }
    return x;
}

__global__ __launch_bounds__(1024)
void k_scan_a() {
    const int t = threadIdx.x;
    const int lane = t & 31, wid = t >> 5;
    const int i = blockIdx.x * 1024 + t;
    int v = (i < N_NODES) ? g_deg[i] : 0;
    int x = warp_incl_scan(v, lane);
    __shared__ int wsum[32];
    if (lane == 31) wsum[wid] = x;
    __syncthreads();
    if (wid == 0) {
        int s = wsum[lane];
        s = warp_incl_scan(s, lane);
        wsum[lane] = s;
    }
    __syncthreads();
    int ex = x - v + (wid > 0 ? wsum[wid - 1] : 0);
    if (i < N_NODES) g_rowstart[i] = ex;
    if (t == 1023) g_blocksum[blockIdx.x] = ex + v;
}

__global__ __launch_bounds__(128)
void k_scan_b() {
    const int t = threadIdx.x;
    const int lane = t & 31, wid = t >> 5;
    int v = (t < SCAN_BLOCKS) ? g_blocksum[t] : 0;
    int x = warp_incl_scan(v, lane);
    __shared__ int wsum[4];
    if (lane == 31) wsum[wid] = x;
    __syncthreads();
    int add = 0;
#pragma unroll
    for (int w = 0; w < 4; w++)
        if (w < wid) add += wsum[w];
    if (t < SCAN_BLOCKS) g_blockoff[t] = x - v + add;
}

__global__ __launch_bounds__(1024)
void k_scan_c() {
    const int i = blockIdx.x * 1024 + threadIdx.x;
    if (i < N_NODES) {
        g_rowstart[i] += g_blockoff[blockIdx.x];
        g_dinv[i] = rsqrtf((float)(g_deg[i] + 1));  // +1 self loop
    }
}

// CSR bucket fill, reading src/dst directly from edge_index
__global__ __launch_bounds__(256)
void k_fill(const void* eidx) {
    int e = blockIdx.x * blockDim.x + threadIdx.x;
    if (e >= N_EDGES) return;
    int s, d;
    if (g_flag) {
        const long long* p = (const long long*)eidx;
        s = (int)p[e];
        d = (int)p[N_EDGES + e];
    } else {
        const int* p = (const int*)eidx;
        s = p[e];
        d = p[N_EDGES + e];
    }
    int pos = atomicAdd(&g_cursor[d], 1);
    g_csr_src[g_rowstart[d] + pos] = s;
}

// ---------------- tf32 helpers ----------------
__device__ __forceinline__ float to_tf32(float x) {
    float r;
    asm("cvt.rna.tf32.f32 %0, %1;" : "=f"(r) : "f"(x));
    return r;
}

__device__ __forceinline__ void mma_tf32(float c[4], const uint32_t a[4], const uint32_t b[2]) {
    asm volatile(
        "mma.sync.aligned.m16n8k8.row.col.f32.tf32.tf32.f32 "
        "{%0,%1,%2,%3}, {%4,%5,%6,%7}, {%8,%9}, {%0,%1,%2,%3};"
        : "+f"(c[0]), "+f"(c[1]), "+f"(c[2]), "+f"(c[3])
        : "r"(a[0]), "r"(a[1]), "r"(a[2]), "r"(a[3]), "r"(b[0]), "r"(b[1]));
}

// ---------------- GEMM1: XW1 via tf32 MMA, bf16 output ----------------
__global__ __launch_bounds__(256)
void k_gemm1_tf32(const float* __restrict__ A, const float* __restrict__ B) {
    __shared__ float As[128][36];
    __shared__ float Bs[32][136];

    const int tid = threadIdx.x;
    const int m0 = blockIdx.x * 128;
    const int wid = tid >> 5, lane = tid & 31;
    const int g = lane >> 2, tig = lane & 3;
    const int warp_m = wid >> 1;
    const int warp_n = wid & 1;
    const int mbase = warp_m * 32;
    const int nbase = warp_n * 64;

    float c[2][8][4];
#pragma unroll
    for (int mt = 0; mt < 2; mt++)
#pragma unroll
        for (int nt = 0; nt < 8; nt++)
#pragma unroll
            for (int i = 0; i < 4; i++) c[mt][nt][i] = 0.0f;

    for (int k0 = 0; k0 < F_IN; k0 += 32) {
#pragma unroll
        for (int s = 0; s < 4; s++) {
            int slot = tid + s * 256;
            int r = slot >> 3;
            int kk = (slot & 7) * 4;
            int gr = m0 + r;
            float4 v = make_float4(0.f, 0.f, 0.f, 0.f);
            if (gr < N_NODES) v = *reinterpret_cast<const float4*>(&A[(size_t)gr * F_IN + k0 + kk]);
            As[r][kk + 0] = to_tf32(v.x);
            As[r][kk + 1] = to_tf32(v.y);
            As[r][kk + 2] = to_tf32(v.z);
            As[r][kk + 3] = to_tf32(v.w);
        }
#pragma unroll
        for (int s = 0; s < 4; s++) {
            int slot = tid + s * 256;
            int kr = slot >> 5;
            int n = (slot & 31) * 4;
            float4 v = *reinterpret_cast<const float4*>(&B[(size_t)(k0 + kr) * HID + n]);
            Bs[kr][n + 0] = to_tf32(v.x);
            Bs[kr][n + 1] = to_tf32(v.y);
            Bs[kr][n + 2] = to_tf32(v.z);
            Bs[kr][n + 3] = to_tf32(v.w);
        }
        __syncthreads();

#pragma unroll
        for (int kk = 0; kk < 4; kk++) {
            const int kb = kk * 8;
            uint32_t a[2][4];
#pragma unroll
            for (int mt = 0; mt < 2; mt++) {
                int m = mbase + mt * 16 + g;
                a[mt][0] = __float_as_uint(As[m][kb + tig]);
                a[mt][1] = __float_as_uint(As[m + 8][kb + tig]);
                a[mt][2] = __float_as_uint(As[m][kb + tig + 4]);
                a[mt][3] = __float_as_uint(As[m + 8][kb + tig + 4]);
            }
            uint32_t b[8][2];
#pragma unroll
            for (int nt = 0; nt < 8; nt++) {
                int n = nbase + nt * 8 + g;
                b[nt][0] = __float_as_uint(Bs[kb + tig][n]);
                b[nt][1] = __float_as_uint(Bs[kb + tig + 4][n]);
            }
#pragma unroll
            for (int mt = 0; mt < 2; mt++)
#pragma unroll
                for (int nt = 0; nt < 8; nt++)
                    mma_tf32(c[mt][nt], a[mt], b[nt]);
        }
        __syncthreads();
    }

#pragma unroll
    for (int mt = 0; mt < 2; mt++) {
#pragma unroll
        for (int nt = 0; nt < 8; nt++) {
            int row0 = m0 + mbase + mt * 16 + g;
            int cp = (nbase + nt * 8) / 2 + tig;
            if (row0 < N_NODES)
                g_xw_bf[(size_t)row0 * 64 + cp] = f2_to_bf2(c[mt][nt][0], c[mt][nt][1]);
            int row1 = row0 + 8;
            if (row1 < N_NODES)
                g_xw_bf[(size_t)row1 * 64 + cp] = f2_to_bf2(c[mt][nt][2], c[mt][nt][3]);
        }
    }
}

// ---------------- GEMM2: H @ W2 via tf32 MMA, bf16 A input + bf16 output ----------------
__global__ __launch_bounds__(256)
void k_gemm2_tf32(const float* __restrict__ B) {
    __shared__ float As[128][36];
    __shared__ float Bs[128][40];

    const int tid = threadIdx.x;
    const int m0 = blockIdx.x * 128;
    const int wid = tid >> 5, lane = tid & 31;
    const int g = lane >> 2, tig = lane & 3;

#pragma unroll
    for (int s = 0; s < 4; s++) {
        int slot = tid + s * 256;
        int r = slot >> 3;
        int n = (slot & 7) * 4;
        float4 v = *reinterpret_cast<const float4*>(&B[(size_t)r * N_CLS + n]);
        Bs[r][n + 0] = to_tf32(v.x);
        Bs[r][n + 1] = to_tf32(v.y);
        Bs[r][n + 2] = to_tf32(v.z);
        Bs[r][n + 3] = to_tf32(v.w);
    }

    float c[4][4];
#pragma unroll
    for (int nt = 0; nt < 4; nt++)
#pragma unroll
        for (int i = 0; i < 4; i++) c[nt][i] = 0.0f;

    const uint2* h2 = reinterpret_cast<const uint2*>(g_h_bf);  // 32 uint2 per row
    for (int k0 = 0; k0 < HID; k0 += 32) {
#pragma unroll
        for (int s = 0; s < 4; s++) {
            int slot = tid + s * 256;
            int r = slot >> 3;
            int kk = (slot & 7) * 4;
            int gr = m0 + r;
            uint2 u = make_uint2(0u, 0u);
            if (gr < N_NODES) u = h2[(size_t)gr * 32 + (k0 >> 2) + (slot & 7)];
            float2 f0 = bf2_to_f2(u.x);
            float2 f1 = bf2_to_f2(u.y);
            As[r][kk + 0] = f0.x;
            As[r][kk + 1] = f0.y;
            As[r][kk + 2] = f1.x;
            As[r][kk + 3] = f1.y;
        }
        __syncthreads();

#pragma unroll
        for (int kk = 0; kk < 4; kk++) {
            const int kb = kk * 8;
            const int m = wid * 16 + g;
            uint32_t a[4];
            a[0] = __float_as_uint(As[m][kb + tig]);
            a[1] = __float_as_uint(As[m + 8][kb + tig]);
            a[2] = __float_as_uint(As[m][kb + tig + 4]);
            a[3] = __float_as_uint(As[m + 8][kb + tig + 4]);
#pragma unroll
            for (int nt = 0; nt < 4; nt++) {
                uint32_t b[2];
                int n = nt * 8 + g;
                b[0] = __float_as_uint(Bs[k0 + kb + tig][n]);
                b[1] = __float_as_uint(Bs[k0 + kb + tig + 4][n]);
                mma_tf32(c[nt], a, b);
            }
        }
        __syncthreads();
    }

    const int row0 = m0 + wid * 16 + g;
#pragma unroll
    for (int nt = 0; nt < 4; nt++) {
        int cp = nt * 4 + tig;
        if (row0 < N_NODES)
            g_hw2_bf[(size_t)row0 * 16 + cp] = f2_to_bf2(c[nt][0], c[nt][1]);
        if (row0 + 8 < N_NODES)
            g_hw2_bf[(size_t)(row0 + 8) * 16 + cp] = f2_to_bf2(c[nt][2], c[nt][3]);
    }
}

// ---------------- layer-1 aggregation: warp per node, bf16 gathers, fp32 accum ----------------
__global__ __launch_bounds__(256)
void k_agg1(const float* __restrict__ b1) {
    int node = (blockIdx.x * blockDim.x + threadIdx.x) >> 5;
    int lane = threadIdx.x & 31;
    if (node >= N_NODES) return;
    float di = g_dinv[node];
    const uint2* xw2 = reinterpret_cast<const uint2*>(g_xw_bf);  // 32 uint2 per node
    uint2 sv = xw2[(size_t)node * 32 + lane];
    float2 s0 = bf2_to_f2(sv.x), s1 = bf2_to_f2(sv.y);
    float w0 = di * di;
    float4 acc = make_float4(s0.x * w0, s0.y * w0, s1.x * w0, s1.y * w0);
    int start = g_rowstart[node];
    int cnt = g_deg[node];
#pragma unroll 8
    for (int e = 0; e < cnt; e++) {
        int s = g_csr_src[start + e];
        float w = di * g_dinv[s];
        uint2 v = xw2[(size_t)s * 32 + lane];
        float2 f0 = bf2_to_f2(v.x), f1 = bf2_to_f2(v.y);
        acc.x += w * f0.x;
        acc.y += w * f0.y;
        acc.z += w * f1.x;
        acc.w += w * f1.y;
    }
    float4 bb = reinterpret_cast<const float4*>(b1)[lane];
    acc.x = fmaxf(acc.x + bb.x, 0.0f);
    acc.y = fmaxf(acc.y + bb.y, 0.0f);
    acc.z = fmaxf(acc.z + bb.z, 0.0f);
    acc.w = fmaxf(acc.w + bb.w, 0.0f);
    uint2 outv;
    outv.x = f2_to_bf2(acc.x, acc.y);
    outv.y = f2_to_bf2(acc.z, acc.w);
    reinterpret_cast<uint2*>(g_h_bf)[(size_t)node * 32 + lane] = outv;
}

// ---------------- layer-2 aggregation + bias + log_softmax ----------------
// 16 lanes per node, 2 nodes per warp. Each sublane handles 2 classes (uint32 = bf16x2).
__global__ __launch_bounds__(256)
void k_agg2(const float* __restrict__ b2, float* __restrict__ out) {
    int warp = (blockIdx.x * blockDim.x + threadIdx.x) >> 5;
    int lane = threadIdx.x & 31;
    int half = lane >> 4;            // 0 or 1
    int sub = lane & 15;             // 0..15
    int node = warp * 2 + half;
    if (node >= N_NODES) return;
    float di = g_dinv[node];
    float w0 = di * di;
    uint32_t sv = g_hw2_bf[(size_t)node * 16 + sub];
    float2 s = bf2_to_f2(sv);
    float acc0 = w0 * s.x, acc1 = w0 * s.y;
    int start = g_rowstart[node];
    int cnt = g_deg[node];
#pragma unroll 8
    for (int e = 0; e < cnt; e++) {
        int sr = g_csr_src[start + e];
        float w = di * g_dinv[sr];
        float2 f = bf2_to_f2(g_hw2_bf[(size_t)sr * 16 + sub]);
        acc0 += w * f.x;
        acc1 += w * f.y;
    }
    float2 bbv = reinterpret_cast<const float2*>(b2)[sub];
    acc0 += bbv.x;
    acc1 += bbv.y;
    // log_softmax over 32 classes = 16 sublanes x 2
    float m = fmaxf(acc0, acc1);
#pragma unroll
    for (int off = 8; off > 0; off >>= 1)
        m = fmaxf(m, __shfl_xor_sync(0xFFFFFFFFu, m, off));
    float sum = expf(acc0 - m) + expf(acc1 - m);
#pragma unroll
    for (int off = 8; off > 0; off >>= 1)
        sum += __shfl_xor_sync(0xFFFFFFFFu, sum, off);
    float ls = m + logf(sum);
    *reinterpret_cast<float2*>(&out[(size_t)node * N_CLS + sub * 2]) =
        make_float2(acc0 - ls, acc1 - ls);
}

// ---------------- launch ----------------
extern "C" void kernel_launch(void* const* d_in, const int* in_sizes, int n_in,
                              void* d_out, int out_size) {
    const float* features = nullptr;
    const void*  eidx = nullptr;
    const float* W1 = nullptr;
    const float* b1 = nullptr;
    const float* W2 = nullptr;
    const float* b2 = nullptr;
    for (int i = 0; i < n_in; i++) {
        switch (in_sizes[i]) {
            case N_NODES * F_IN: features = (const float*)d_in[i]; break;
            case 2 * N_EDGES:    eidx = d_in[i]; break;
            case F_IN * HID:     W1 = (const float*)d_in[i]; break;
            case HID:            b1 = (const float*)d_in[i]; break;
            case HID * N_CLS:    W2 = (const float*)d_in[i]; break;
            case N_CLS:          b2 = (const float*)d_in[i]; break;
            default: break;
        }
    }

    // lazily-created side stream + events (host-side resources only; created once)
    static cudaStream_t s2 = nullptr;
    static cudaEvent_t ev_fork = nullptr, ev_join = nullptr;
    if (s2 == nullptr) {
        cudaStreamCreateWithFlags(&s2, cudaStreamNonBlocking);
        cudaEventCreateWithFlags(&ev_fork, cudaEventDisableTiming);
        cudaEventCreateWithFlags(&ev_join, cudaEventDisableTiming);
    }

    // fork: preprocessing chain on s2 (launched first), GEMM1 on the main stream
    cudaEventRecord(ev_fork, 0);
    cudaStreamWaitEvent(s2, ev_fork, 0);

    k_init<<<(N_NODES + 255) / 256, 256, 0, s2>>>((const int*)eidx);
    k_convert<<<(N_EDGES + 255) / 256, 256, 0, s2>>>(eidx);
    k_scan_a<<<SCAN_BLOCKS, 1024, 0, s2>>>();
    k_scan_b<<<1, 128, 0, s2>>>();
    k_scan_c<<<SCAN_BLOCKS, 1024, 0, s2>>>();
    k_fill<<<(N_EDGES + 255) / 256, 256, 0, s2>>>(eidx);
    cudaEventRecord(ev_join, s2);

    // concurrent with preprocessing: layer-1 GEMM (tf32 tensor cores)
    {
        int grid = (N_NODES + 127) / 128;  // 782
        k_gemm1_tf32<<<grid, 256>>>(features, W1);
    }

    // join: aggregation needs both GEMM1 and CSR
    cudaStreamWaitEvent(0, ev_join, 0);

    k_agg1<<<(N_NODES * 32 + 255) / 256, 256>>>(b1);

    // layer 2: HW2 (tf32) then aggregate+bias+log_softmax
    {
        int grid = (N_NODES + 127) / 128;  // 782
        k_gemm2_tf32<<<grid, 256>>>(W2);
    }
    k_agg2<<<((N_NODES / 2) * 32 + 255) / 256, 256>>>(b2, (float*)d_out);
}